// round 15
// baseline (speedup 1.0000x reference)
#include <cuda_runtime.h>
#include <cstdint>

#define BATCH 256
#define L 4096
#define H 128

// ---------- packed f32x2 helpers (Blackwell sm_103a) ----------
__device__ __forceinline__ uint64_t pack2f(float a, float b) {
    uint64_t r; asm("mov.b64 %0, {%1, %2};" : "=l"(r) : "f"(a), "f"(b)); return r;
}
__device__ __forceinline__ float hsum2(uint64_t v) {
    float a, b; asm("mov.b64 {%0, %1}, %2;" : "=f"(a), "=f"(b) : "l"(v)); return a + b;
}
__device__ __forceinline__ uint64_t ffma2(uint64_t a, uint64_t b, uint64_t c) {
    uint64_t d; asm("fma.rn.f32x2 %0, %1, %2, %3;" : "=l"(d) : "l"(a), "l"(b), "l"(c)); return d;
}
__device__ __forceinline__ uint64_t fadd2(uint64_t a, uint64_t b) {
    uint64_t d; asm("add.rn.f32x2 %0, %1, %2;" : "=l"(d) : "l"(a), "l"(b)); return d;
}
__device__ __forceinline__ float elu1(float x) {
    return fmaxf(x, 0.f) + (__expf(fminf(x, 0.f)) - 1.f);
}
#define BAR_A() asm volatile("bar.sync 1, 128;" ::: "memory")
#define BAR_B() asm volatile("bar.sync 2, 128;" ::: "memory")
#define CFENCE() asm volatile("" ::: "memory")

// One CTA = 2 batch elements, 256 threads, two DECOUPLED warp-groups:
//   Group A (warps 0-3): layer-1 recurrence. Thread owns unit u=(warp&3)*32+lane,
//     full 128-k dot for both batches (64 packed weight regs, pure-broadcast LDS,
//     zero reduction shuffles). h1 kept in an 8-slot ring (slot n&7).
//     Per step: bar.sync 1 (group-internal) then publish flagA=n+1.
//     Backpressure: waits until flagB >= n-7 before overwriting ring slot n&7.
//   Group B (warps 4-7): layer-2 recurrence + output head, lagged behind A.
//     Gates on flagA >= m+1, reads h1 ring slot m&7, bar.sync 2, publishes flagB.
// Each SMSP hosts one A-warp and one B-warp (warp&3 mapping) that are now
// INDEPENDENTLY paced: A's LSU bursts overlap B's FMA phases and vice versa.
// Deadlock-free: A waits only on B's step n-8; B waits only on A's step m.
__global__ void __launch_bounds__(256, 1)
rnn_scan_kernel(const int* __restrict__ x,
                const float* __restrict__ W_in,
                const float* __restrict__ W_c,
                const float* __restrict__ W_out,
                const float* __restrict__ b_out,
                float* __restrict__ out)
{
    __shared__ __align__(16) float sh_h1[8][2 * H];     // h1 ring: slot n&7 (8 KB)
    __shared__ __align__(16) float sh_h2[2][2 * H];     // B ping-pong
    __shared__ __align__(16) float sh_r[3 * H];
    __shared__ __align__(16) float sh_prod[16][2 * H];  // head ring (16 KB)
    __shared__ uint8_t sh_x[2 * L];                     // 8 KB
    __shared__ float sh_acc[4][2];
    __shared__ volatile unsigned sh_flagA;              // A's published step count
    __shared__ volatile unsigned sh_flagB;              // B's published step count

    const int tid  = threadIdx.x;
    const int warp = tid >> 5;
    const int lane = tid & 31;
    const int unit = (warp & 3) * 32 + lane;
    const bool isA = (warp < 4);
    const int b0   = blockIdx.x * 2;

    // ---- stage x; r table; zero initial states; flags ----
    const int* xg = x + (size_t)b0 * L;
    #pragma unroll 4
    for (int idx = tid; idx < 2 * L; idx += 256) sh_x[idx] = (uint8_t)xg[idx];
    if (tid < 2 * H) sh_r[tid] = elu1(W_in[tid]);
    if (tid < H)     sh_r[2 * H + tid] = 0.f;
    if (tid < 2 * H) { sh_h1[7][tid] = 0.f; sh_h2[1][tid] = 0.f; }
    if (tid == 0) { sh_flagA = 0u; sh_flagB = 0u; }

    // ---- weights: this thread's layer, full column `unit` ----
    const float* Wl = W_c + (isA ? 0 : H * H);
    uint64_t w[64];
    #pragma unroll
    for (int j = 0; j < 64; ++j)
        w[j] = pack2f(Wl[(2 * j) * H + unit], Wl[(2 * j + 1) * H + unit]);

    const float wout_u = W_out[unit];
    const float bout   = b_out[0];
    float hacc0 = 0.f, hacc1 = 0.f;

    __syncthreads();

    if (isA) {
        // ===================== GROUP A: layer-1 scan =====================
        for (int n = 0; n < L; ++n) {
            // backpressure: slot n&7 was read by B at its step n-8
            if (n >= 8) { while (sh_flagB + 7u < (unsigned)n) { } CFENCE(); }

            const float* hr = &sh_h1[(n + 7) & 7][0];   // h1(n-1)
            float*       hw = &sh_h1[n & 7][0];
            const int   pr0 = n ? (int)sh_x[n - 1]     : 2;
            const int   pr1 = n ? (int)sh_x[L + n - 1] : 2;
            const float rv0 = sh_r[pr0 * H + unit];
            const float rv1 = sh_r[pr1 * H + unit];

            uint64_t a0=0,a1=0,a2=0,a3=0,c0=0,c1=0,c2=0,c3=0;
            #pragma unroll
            for (int j = 0; j < 16; ++j) {
                const int o = 8 * j;
                const ulonglong2 u0 = *(const ulonglong2*)(hr + o);
                const ulonglong2 u1 = *(const ulonglong2*)(hr + o + 4);
                const ulonglong2 v0 = *(const ulonglong2*)(hr + H + o);
                const ulonglong2 v1 = *(const ulonglong2*)(hr + H + o + 4);
                a0 = ffma2(w[4*j],   u0.x, a0);
                a1 = ffma2(w[4*j+1], u0.y, a1);
                a2 = ffma2(w[4*j+2], u1.x, a2);
                a3 = ffma2(w[4*j+3], u1.y, a3);
                c0 = ffma2(w[4*j],   v0.x, c0);
                c1 = ffma2(w[4*j+1], v0.y, c1);
                c2 = ffma2(w[4*j+2], v1.x, c2);
                c3 = ffma2(w[4*j+3], v1.y, c3);
            }
            const float d0 = hsum2(fadd2(fadd2(a0, a1), fadd2(a2, a3)));
            const float d1 = hsum2(fadd2(fadd2(c0, c1), fadd2(c2, c3)));
            hw[unit]     = elu1(d0) + rv0;
            hw[H + unit] = elu1(d1) + rv1;

            BAR_A();                        // group A's STS drained
            if (tid == 0) sh_flagA = (unsigned)(n + 1);
        }
    } else {
        // ============ GROUP B: layer-2 scan + output head (lags A) ============
        for (int m = 0; m < L; ++m) {
            while (sh_flagA < (unsigned)(m + 1)) { } CFENCE();

            const float* hr = &sh_h2[(m + 1) & 1][0];   // h2(m-1)
            float*       hw = &sh_h2[m & 1][0];
            const float h1m0 = sh_h1[m & 7][unit];      // h1(m)
            const float h1m1 = sh_h1[m & 7][H + unit];

            uint64_t a0=0,a1=0,a2=0,a3=0,c0=0,c1=0,c2=0,c3=0;
            #pragma unroll
            for (int j = 0; j < 16; ++j) {
                const int o = 8 * j;
                const ulonglong2 u0 = *(const ulonglong2*)(hr + o);
                const ulonglong2 u1 = *(const ulonglong2*)(hr + o + 4);
                const ulonglong2 v0 = *(const ulonglong2*)(hr + H + o);
                const ulonglong2 v1 = *(const ulonglong2*)(hr + H + o + 4);
                a0 = ffma2(w[4*j],   u0.x, a0);
                a1 = ffma2(w[4*j+1], u0.y, a1);
                a2 = ffma2(w[4*j+2], u1.x, a2);
                a3 = ffma2(w[4*j+3], u1.y, a3);
                c0 = ffma2(w[4*j],   v0.x, c0);
                c1 = ffma2(w[4*j+1], v0.y, c1);
                c2 = ffma2(w[4*j+2], v1.x, c2);
                c3 = ffma2(w[4*j+3], v1.y, c3);
            }
            const float d0 = hsum2(fadd2(fadd2(a0, a1), fadd2(a2, a3)));
            const float d1 = hsum2(fadd2(fadd2(c0, c1), fadd2(c2, c3)));
            const float h2n0 = elu1(d0) + h1m0;
            const float h2n1 = elu1(d1) + h1m1;
            hw[unit]     = h2n0;
            hw[H + unit] = h2n1;
            sh_prod[m & 15][unit]     = h2n0 * wout_u;
            sh_prod[m & 15][H + unit] = h2n1 * wout_u;

            // amortized head: every 8 steps, warp wb=warp-4 reduces slots
            // m-8+2*wb, m-8+2*wb+1 (written steps m-8..m-1; overwrite at u+16 > m)
            if ((m & 7) == 0 && m >= 8) {
                const int wb = warp - 4;
                #pragma unroll
                for (int e = 0; e < 2; ++e) {
                    const int u = m - 8 + 2 * wb + e;
                    #pragma unroll
                    for (int b = 0; b < 2; ++b) {
                        const float4 v = *(const float4*)&sh_prod[u & 15][b * H + lane * 4];
                        float sr = (v.x + v.y) + (v.z + v.w);
                        #pragma unroll
                        for (int off = 16; off; off >>= 1)
                            sr += __shfl_xor_sync(0xffffffffu, sr, off);
                        if (lane == 0) {
                            const float logit = sr + bout;
                            const int   xt    = sh_x[b * L + u];
                            const float mm    = fmaxf(logit, 0.f);
                            const float lse   = mm + __logf(__expf(-mm) + __expf(logit - mm));
                            const float gv    = 0.5f * ((xt ? logit : 0.f) - lse);
                            if (b == 0) hacc0 += gv; else hacc1 += gv;
                        }
                    }
                }
            }

            BAR_B();                        // group B's STS drained
            if (tid == 128) sh_flagB = (unsigned)(m + 1);
        }

        // epilogue: last 8 slots [L-8, L-1]
        {
            const int wb = warp - 4;
            #pragma unroll
            for (int e = 0; e < 2; ++e) {
                const int u = L - 8 + 2 * wb + e;
                #pragma unroll
                for (int b = 0; b < 2; ++b) {
                    const float4 v = *(const float4*)&sh_prod[u & 15][b * H + lane * 4];
                    float sr = (v.x + v.y) + (v.z + v.w);
                    #pragma unroll
                    for (int off = 16; off; off >>= 1)
                        sr += __shfl_xor_sync(0xffffffffu, sr, off);
                    if (lane == 0) {
                        const float logit = sr + bout;
                        const int   xt    = sh_x[b * L + u];
                        const float mm    = fmaxf(logit, 0.f);
                        const float lse   = mm + __logf(__expf(-mm) + __expf(logit - mm));
                        const float gv    = 0.5f * ((xt ? logit : 0.f) - lse);
                        if (b == 0) hacc0 += gv; else hacc1 += gv;
                    }
                }
            }
        }
        if (lane == 0) { sh_acc[warp - 4][0] = hacc0; sh_acc[warp - 4][1] = hacc1; }
    }

    __syncthreads();
    if (tid < 2) {
        float a = 0.f;
        #pragma unroll
        for (int wq = 0; wq < 4; ++wq) a += sh_acc[wq][tid];
        out[b0 + tid] = a;
    }
}

extern "C" void kernel_launch(void* const* d_in, const int* in_sizes, int n_in,
                              void* d_out, int out_size)
{
    const int*   x     = (const int*)  d_in[0];
    const float* W_in  = (const float*)d_in[1];
    const float* W_c   = (const float*)d_in[2];
    const float* W_out = (const float*)d_in[3];
    const float* b_out = (const float*)d_in[4];

    rnn_scan_kernel<<<BATCH / 2, 256>>>(x, W_in, W_c, W_out, b_out, (float*)d_out);
}

// round 17
// speedup vs baseline: 1.0628x; 1.0628x over previous
#include <cuda_runtime.h>
#include <cstdint>

#define BATCH 256
#define L 4096
#define H 128

// ---------- packed f32x2 helpers ----------
__device__ __forceinline__ uint64_t pack2f(float a, float b) {
    uint64_t r; asm("mov.b64 %0, {%1, %2};" : "=l"(r) : "f"(a), "f"(b)); return r;
}
__device__ __forceinline__ float hsum2(uint64_t v) {
    float a, b; asm("mov.b64 {%0, %1}, %2;" : "=f"(a), "=f"(b) : "l"(v)); return a + b;
}
__device__ __forceinline__ uint64_t ffma2(uint64_t a, uint64_t b, uint64_t c) {
    uint64_t d; asm("fma.rn.f32x2 %0, %1, %2, %3;" : "=l"(d) : "l"(a), "l"(b), "l"(c)); return d;
}
__device__ __forceinline__ uint64_t fadd2(uint64_t a, uint64_t b) {
    uint64_t d; asm("add.rn.f32x2 %0, %1, %2;" : "=l"(d) : "l"(a), "l"(b)); return d;
}
__device__ __forceinline__ float elu1(float x) {
    return fmaxf(x, 0.f) + (__expf(fminf(x, 0.f)) - 1.f);
}
// tf32 helpers (validated in R8)
__device__ __forceinline__ uint32_t tf32u(float x) {
    uint32_t u; asm("cvt.rna.tf32.f32 %0, %1;" : "=r"(u) : "f"(x)); return u;
}
__device__ __forceinline__ float tf32r(float x) { return __uint_as_float(tf32u(x)); }
// m16n8k8 tf32 MMA, accumulate in-place (fallback HMMA — compiles at compute_103)
__device__ __forceinline__ void mma8(float* d,
                                     const uint32_t* a, uint32_t b0, uint32_t b1)
{
    asm volatile("mma.sync.aligned.m16n8k8.row.col.f32.tf32.tf32.f32 "
                 "{%0,%1,%2,%3}, {%4,%5,%6,%7}, {%8,%9}, {%0,%1,%2,%3};"
                 : "+f"(d[0]), "+f"(d[1]), "+f"(d[2]), "+f"(d[3])
                 : "r"(a[0]), "r"(a[1]), "r"(a[2]), "r"(a[3]), "r"(b0), "r"(b1));
}
// k-permutation: pos(k) = (k&~7)|((k&3)<<1)|((k>>2)&1)  (validated in R8)
__device__ __forceinline__ int posk(int k) {
    return (k & ~7) | ((k & 3) << 1) | ((k >> 2) & 1);
}

// HYBRID PIPE SPLIT. One CTA = 2 batches, 256 threads.
// Warps 0-3 (A, FMA pipe): layer-1. Thread owns unit=(warp&3)*32+lane, full
//   128-k f32 dot for both batches (64 packed weight regs, broadcast LDS, no
//   reduction shuffles). Exact R14-A body.
// Warps 4-7 (B, TENSOR pipe): layer-2 lagged one step, via m16n8k8 tf32 HMMA
//   (R8's validated mapping). Each warp owns 32 output rows (2 m16 rowtiles);
//   B operand = h2(t-1) (tf32, k-permuted SMEM, batches in cols 0/1).
//   Epilogue lanes lr==0 apply elu + h1 and store h2/prod. Head amortized on B.
// Iteration n: A computes h1(n) (n<L); B computes h2(n-1) (n>=1) from
// h2(n-2) and h1(n-1) — independent halves, ONE __syncthreads joins them.
// Each SMSP hosts one A-warp (FMA-bound) and one B-warp (tensor-bound):
// different pipes, so their work overlaps instead of queueing.
__global__ void __launch_bounds__(256, 1)
rnn_scan_kernel(const int* __restrict__ x,
                const float* __restrict__ W_in,
                const float* __restrict__ W_c,
                const float* __restrict__ W_out,
                const float* __restrict__ b_out,
                float* __restrict__ out)
{
    __shared__ __align__(16) float sh_h1[2][2 * H];     // h1(m) in [m&1][b*H+unit], f32
    __shared__ __align__(16) float sh_h2[2][2 * H];     // h2(m) in [m&1][b*H+posk(u)], tf32
    __shared__ __align__(16) float sh_r[3 * H];
    __shared__ __align__(16) float sh_prod[32][2 * H];  // 32 KB head ring (perm order)
    __shared__ uint8_t sh_x[2 * L];
    __shared__ float sh_acc[4][2];

    const int tid  = threadIdx.x;
    const int warp = tid >> 5;
    const int lane = tid & 31;
    const bool isA = (warp < 4);
    const int b0   = blockIdx.x * 2;

    // ---- stage x; r table; zero initial states (buffers [1] = step -1) ----
    const int* xg = x + (size_t)b0 * L;
    #pragma unroll 4
    for (int idx = tid; idx < 2 * L; idx += 256) sh_x[idx] = (uint8_t)xg[idx];
    if (tid < 2 * H) sh_r[tid] = elu1(W_in[tid]);
    if (tid < H)     sh_r[2 * H + tid] = 0.f;
    if (tid < 2 * H) { sh_h1[1][tid] = 0.f; sh_h2[0][tid] = 0.f; sh_h2[1][tid] = 0.f; }

    const float bout = b_out[0];
    float hacc0 = 0.f, hacc1 = 0.f;

    if (isA) {
        // =========== GROUP A prologue: layer-1 weights (full column) ===========
        const int unit = (warp & 3) * 32 + lane;
        uint64_t w[64];
        #pragma unroll
        for (int j = 0; j < 64; ++j)
            w[j] = pack2f(W_c[(2 * j) * H + unit], W_c[(2 * j + 1) * H + unit]);
        __syncthreads();

        for (int n = 0; n <= L; ++n) {
            if (n < L) {
                const float* hr = &sh_h1[(n + 1) & 1][0];   // h1(n-1)
                float*       hw = &sh_h1[n & 1][0];
                const int   pr0 = n ? (int)sh_x[n - 1]     : 2;
                const int   pr1 = n ? (int)sh_x[L + n - 1] : 2;
                const float rv0 = sh_r[pr0 * H + unit];
                const float rv1 = sh_r[pr1 * H + unit];

                uint64_t a0=0,a1=0,a2=0,a3=0,c0=0,c1=0,c2=0,c3=0;
                #pragma unroll
                for (int j = 0; j < 16; ++j) {
                    const int o = 8 * j;
                    const ulonglong2 u0 = *(const ulonglong2*)(hr + o);
                    const ulonglong2 u1 = *(const ulonglong2*)(hr + o + 4);
                    const ulonglong2 v0 = *(const ulonglong2*)(hr + H + o);
                    const ulonglong2 v1 = *(const ulonglong2*)(hr + H + o + 4);
                    a0 = ffma2(w[4*j],   u0.x, a0);
                    a1 = ffma2(w[4*j+1], u0.y, a1);
                    a2 = ffma2(w[4*j+2], u1.x, a2);
                    a3 = ffma2(w[4*j+3], u1.y, a3);
                    c0 = ffma2(w[4*j],   v0.x, c0);
                    c1 = ffma2(w[4*j+1], v0.y, c1);
                    c2 = ffma2(w[4*j+2], v1.x, c2);
                    c3 = ffma2(w[4*j+3], v1.y, c3);
                }
                const float d0 = hsum2(fadd2(fadd2(a0, a1), fadd2(a2, a3)));
                const float d1 = hsum2(fadd2(fadd2(c0, c1), fadd2(c2, c3)));
                hw[unit]     = elu1(d0) + rv0;
                hw[H + unit] = elu1(d1) + rv1;
            }
            __syncthreads();
        }
    } else {
        // ====== GROUP B prologue: layer-2 tf32 A-fragments (2 rowtiles) ======
        const int wb = warp - 4;
        const int lg = lane >> 2;
        const int lr = lane & 3;
        const float* Wc1 = W_c + H * H;

        uint32_t Af[2][16][4];
        int   ra[2], rb[2], pra[2], prb[2];
        float wra[2], wrb[2];
        #pragma unroll
        for (int rt = 0; rt < 2; ++rt) {
            ra[rt]  = 32 * wb + 16 * rt + lg;
            rb[rt]  = ra[rt] + 8;
            pra[rt] = posk(ra[rt]);
            prb[rt] = posk(rb[rt]);
            wra[rt] = W_out[ra[rt]];
            wrb[rt] = W_out[rb[rt]];
            #pragma unroll
            for (int c = 0; c < 16; ++c) {
                const int k0 = 8 * c + lr;
                Af[rt][c][0] = tf32u(Wc1[(k0    ) * H + ra[rt]]);
                Af[rt][c][1] = tf32u(Wc1[(k0    ) * H + rb[rt]]);
                Af[rt][c][2] = tf32u(Wc1[(k0 + 4) * H + ra[rt]]);
                Af[rt][c][3] = tf32u(Wc1[(k0 + 4) * H + rb[rt]]);
            }
        }
        const int  boff = (lg & 1) * H + 2 * lr;   // batch col segment + frag offset
        const bool el   = (lr == 0);
        __syncthreads();

        for (int n = 0; n <= L; ++n) {
            if (n >= 1) {
                const int m = n - 1;
                const float* h2r = &sh_h2[n & 1][0];         // h2(m-1)
                float*       h2w = &sh_h2[(n + 1) & 1][0];   // h2(m)
                const float* h1b = &sh_h1[(n + 1) & 1][0];   // h1(m) = h1(n-1)

                float De[2][4] = {{0,0,0,0},{0,0,0,0}};
                float Do[2][4] = {{0,0,0,0},{0,0,0,0}};
                #pragma unroll
                for (int c = 0; c < 16; c += 2) {
                    const float2 fa = *(const float2*)(h2r + boff + 8 * c);
                    const float2 fb = *(const float2*)(h2r + boff + 8 * c + 8);
                    const uint32_t ba0 = __float_as_uint(fa.x), ba1 = __float_as_uint(fa.y);
                    const uint32_t bb0 = __float_as_uint(fb.x), bb1 = __float_as_uint(fb.y);
                    mma8(De[0], Af[0][c],     ba0, ba1);
                    mma8(De[1], Af[1][c],     ba0, ba1);
                    mma8(Do[0], Af[0][c + 1], bb0, bb1);
                    mma8(Do[1], Af[1][c + 1], bb0, bb1);
                }

                if (el) {   // lanes lr==0 hold cols 0,1 = batches 0,1
                    float* pr = &sh_prod[m & 31][0];
                    #pragma unroll
                    for (int rt = 0; rt < 2; ++rt) {
                        const float da0 = De[rt][0] + Do[rt][0];   // (ra, b0)
                        const float da1 = De[rt][1] + Do[rt][1];   // (ra, b1)
                        const float db0 = De[rt][2] + Do[rt][2];   // (rb, b0)
                        const float db1 = De[rt][3] + Do[rt][3];   // (rb, b1)
                        const float ha0 = h1b[ra[rt]],     ha1 = h1b[H + ra[rt]];
                        const float hb0 = h1b[rb[rt]],     hb1 = h1b[H + rb[rt]];
                        const float ua0 = elu1(da0) + ha0, ua1 = elu1(da1) + ha1;
                        const float ub0 = elu1(db0) + hb0, ub1 = elu1(db1) + hb1;
                        h2w[pra[rt]]     = tf32r(ua0);
                        h2w[H + pra[rt]] = tf32r(ua1);
                        h2w[prb[rt]]     = tf32r(ub0);
                        h2w[H + prb[rt]] = tf32r(ub1);
                        pr[pra[rt]]      = ua0 * wra[rt];
                        pr[H + pra[rt]]  = ua1 * wra[rt];
                        pr[prb[rt]]      = ub0 * wrb[rt];
                        pr[H + prb[rt]]  = ub1 * wrb[rt];
                    }
                }

                // ===== amortized head: every 8 iters, 2 slots per B warp =====
                if ((n & 7) == 0 && n >= 8) {
                    #pragma unroll
                    for (int e = 0; e < 2; ++e) {
                        const int u = n - 10 + 2 * wb + e;
                        if (u >= 0) {
                            #pragma unroll
                            for (int b = 0; b < 2; ++b) {
                                const float4 v = *(const float4*)&sh_prod[u & 31][b * H + lane * 4];
                                float sr = (v.x + v.y) + (v.z + v.w);
                                #pragma unroll
                                for (int off = 16; off; off >>= 1)
                                    sr += __shfl_xor_sync(0xffffffffu, sr, off);
                                if (lane == 0) {
                                    const float logit = sr + bout;
                                    const int   xt    = sh_x[b * L + u];
                                    const float mm    = fmaxf(logit, 0.f);
                                    const float lse   = mm + __logf(__expf(-mm) + __expf(logit - mm));
                                    const float gv    = 0.5f * ((xt ? logit : 0.f) - lse);
                                    if (b == 0) hacc0 += gv; else hacc1 += gv;
                                }
                            }
                        }
                    }
                }
            }
            __syncthreads();
        }

        // ---- epilogue head: slots L-2, L-1 (warps 4,5) ----
        if (wb < 2) {
            const int u = L - 2 + wb;
            #pragma unroll
            for (int b = 0; b < 2; ++b) {
                const float4 v = *(const float4*)&sh_prod[u & 31][b * H + lane * 4];
                float sr = (v.x + v.y) + (v.z + v.w);
                #pragma unroll
                for (int off = 16; off; off >>= 1)
                    sr += __shfl_xor_sync(0xffffffffu, sr, off);
                if (lane == 0) {
                    const float logit = sr + bout;
                    const int   xt    = sh_x[b * L + u];
                    const float mm    = fmaxf(logit, 0.f);
                    const float lse   = mm + __logf(__expf(-mm) + __expf(logit - mm));
                    const float gv    = 0.5f * ((xt ? logit : 0.f) - lse);
                    if (b == 0) hacc0 += gv; else hacc1 += gv;
                }
            }
        }
        if (lane == 0) { sh_acc[wb][0] = hacc0; sh_acc[wb][1] = hacc1; }
    }

    __syncthreads();
    if (tid < 2) {
        float a = 0.f;
        #pragma unroll
        for (int wq = 0; wq < 4; ++wq) a += sh_acc[wq][tid];
        out[b0 + tid] = a;
    }
}

extern "C" void kernel_launch(void* const* d_in, const int* in_sizes, int n_in,
                              void* d_out, int out_size)
{
    const int*   x     = (const int*)  d_in[0];
    const float* W_in  = (const float*)d_in[1];
    const float* W_c   = (const float*)d_in[2];
    const float* W_out = (const float*)d_in[3];
    const float* b_out = (const float*)d_in[4];

    rnn_scan_kernel<<<BATCH / 2, 256>>>(x, W_in, W_c, W_out, b_out, (float*)d_out);
}